// round 11
// baseline (speedup 1.0000x reference)
#include <cuda_runtime.h>

#define IMG_W 512
#define IMG_H 512
#define N_IMG 48            // 16 batch * 3 channels
#define HT 8                // output rows per block strip
#define N_STRIPS (IMG_H / HT)
#define NBLK (N_STRIPS * N_IMG)
#define SW 528              // smem columns: s = x+8; float4-aligned rows
#define NT 256              // 8 warps
#define SM_FLOATS (4 * HT * SW)
#define SMEM_BYTES ((SM_FLOATS + 8) * 4)

// zero-initialized at module load; last block of each launch resets them,
// so every graph replay starts from zero (deterministic).
__device__ double g_acc;
__device__ unsigned int g_cnt;

#define WG_INIT {0.00102838f, 0.00759876f, 0.03600077f, 0.10936069f, \
                 0.21300554f, 0.26601173f, 0.21300554f, 0.10936069f, \
                 0.03600077f, 0.00759876f, 0.00102838f}

__global__ void __launch_bounds__(NT, 3) ssim_fused(const float* __restrict__ pred,
                                                    const float* __restrict__ tgt,
                                                    float* __restrict__ out) {
    extern __shared__ float sm[];
    float* wsum = sm + SM_FLOATS;
    const float wg[11] = WG_INIT;

    const int img  = blockIdx.y;
    const int row0 = blockIdx.x * HT;
    const float* P = pred + (size_t)img * (IMG_W * IMG_H);
    const float* T = tgt  + (size_t)img * (IMG_W * IMG_H);
    const bool interior = (row0 >= 5) && (row0 + HT + 5 <= IMG_H);

    // -------- Vertical pass (streaming accumulators): global -> smem --------
    for (int s = threadIdx.x; s < SW; s += NT) {
        const int x = s - 8;
        if (x < 0 || x >= IMG_W) {
            #pragma unroll
            for (int r = 0; r < HT; r++) {
                sm[(0 * HT + r) * SW + s] = 0.f;
                sm[(1 * HT + r) * SW + s] = 0.f;
                sm[(2 * HT + r) * SW + s] = 0.f;
                sm[(3 * HT + r) * SW + s] = 0.f;
            }
            continue;
        }
        float mp[HT], mt[HT], ms[HT], mq[HT];
        #pragma unroll
        for (int r = 0; r < HT; r++) { mp[r] = 0.f; mt[r] = 0.f; ms[r] = 0.f; mq[r] = 0.f; }

        const float* pc = P + (row0 - 5) * IMG_W + x;
        const float* tc = T + (row0 - 5) * IMG_W + x;
        #pragma unroll
        for (int i = 0; i < HT + 10; i++) {
            float p, t;
            if (interior) {
                p = pc[i * IMG_W];
                t = tc[i * IMG_W];
            } else {
                const int row = row0 - 5 + i;
                const bool ok = (row >= 0) && (row < IMG_H);
                p = ok ? P[row * IMG_W + x] : 0.f;
                t = ok ? T[row * IMG_W + x] : 0.f;
            }
            const float s2 = fmaf(t, t, p * p);   // p^2 + t^2 combined channel
            const float q  = p * t;               // computed once per input row
            // input row i feeds outputs r where 0 <= i-r <= 10 (weight wg[i-r])
            #pragma unroll
            for (int r = 0; r < HT; r++) {
                const int k = i - r;
                if (k >= 0 && k <= 10) {           // folds at compile time
                    mp[r] = fmaf(wg[k], p,  mp[r]);
                    mt[r] = fmaf(wg[k], t,  mt[r]);
                    ms[r] = fmaf(wg[k], s2, ms[r]);
                    mq[r] = fmaf(wg[k], q,  mq[r]);
                }
            }
        }
        #pragma unroll
        for (int r = 0; r < HT; r++) {
            sm[(0 * HT + r) * SW + s] = mp[r];
            sm[(1 * HT + r) * SW + s] = mt[r];
            sm[(2 * HT + r) * SW + s] = ms[r];
            sm[(3 * HT + r) * SW + s] = mq[r];
        }
    }
    __syncthreads();

    // -------- Horizontal pass (4-wide quads) + SSIM formula + reduce --------
    const float C1 = 1e-4f, C2 = 9e-4f;
    float acc = 0.f;
    for (int task = threadIdx.x; task < HT * (IMG_W / 4); task += NT) {
        const int r = task >> 7;       // row within strip
        const int q = task & 127;      // quad: outputs x0 = 4q .. 4q+3
        float h[4][4];
        #pragma unroll
        for (int ch = 0; ch < 4; ch++) {
            const float4* rowp = (const float4*)(sm + (ch * HT + r) * SW);
            float v[20];
            #pragma unroll
            for (int b = 0; b < 5; b++) {
                float4 f = rowp[q + b];   // s = 4q..4q+19 covers taps [4q+3, 4q+16]
                v[4 * b + 0] = f.x; v[4 * b + 1] = f.y;
                v[4 * b + 2] = f.z; v[4 * b + 3] = f.w;
            }
            #pragma unroll
            for (int j = 0; j < 4; j++) {
                float a = 0.f;
                #pragma unroll
                for (int k = 0; k < 11; k++) a = fmaf(wg[k], v[3 + j + k], a);
                h[ch][j] = a;
            }
        }
        #pragma unroll
        for (int j = 0; j < 4; j++) {
            float mx  = h[0][j], my = h[1][j];
            float mx2 = mx * mx, my2 = my * my, mxy = mx * my;
            float sgs  = h[2][j] - mx2 - my2;   // sg_x + sg_y
            float sgxy = h[3][j] - mxy;
            float num = (2.f * mxy + C1) * (2.f * sgxy + C2);
            float den = (mx2 + my2 + C1) * (sgs + C2);
            acc += __fdividef(num, den);
        }
    }

    // block reduction
    #pragma unroll
    for (int off = 16; off; off >>= 1)
        acc += __shfl_down_sync(0xffffffffu, acc, off);
    if ((threadIdx.x & 31) == 0) wsum[threadIdx.x >> 5] = acc;
    __syncthreads();

    if (threadIdx.x == 0) {
        float s = 0.f;
        #pragma unroll
        for (int i = 0; i < NT / 32; i++) s += wsum[i];
        atomicAdd(&g_acc, (double)s);
        __threadfence();
        unsigned int t = atomicAdd(&g_cnt, 1u);
        if (t == NBLK - 1) {
            double tot = atomicAdd(&g_acc, 0.0);   // coherent read (returns old)
            out[0] = 1.0f - (float)(tot / ((double)N_IMG * IMG_W * IMG_H));
            g_acc = 0.0;    // reset for next graph replay
            g_cnt = 0u;
        }
    }
}

extern "C" void kernel_launch(void* const* d_in, const int* in_sizes, int n_in,
                              void* d_out, int out_size) {
    const float* pred = (const float*)d_in[0];
    const float* tgt  = (const float*)d_in[1];

    // 66 KB dynamic smem > 48 KB default: opt-in (host attribute, capture-safe)
    cudaFuncSetAttribute(ssim_fused, cudaFuncAttributeMaxDynamicSharedMemorySize,
                         SMEM_BYTES);

    dim3 grid(N_STRIPS, N_IMG);
    ssim_fused<<<grid, NT, SMEM_BYTES>>>(pred, tgt, (float*)d_out);
}

// round 12
// speedup vs baseline: 2.6673x; 2.6673x over previous
#include <cuda_runtime.h>

#define IMG_W 512
#define IMG_H 512
#define N_IMG 48            // 16 batch * 3 channels
#define HT 8                // output rows per block strip
#define N_STRIPS (IMG_H / HT)
#define NBLK (N_STRIPS * N_IMG)
#define SW 528              // smem columns: s = x+8; float4-aligned rows
#define NT 256              // 8 warps
#define SM_FLOATS (4 * HT * SW)
#define SMEM_BYTES ((SM_FLOATS + 8) * 4)

typedef unsigned long long u64;

// zero-initialized at module load; last block of each launch resets them,
// so every graph replay starts from zero (deterministic).
__device__ double g_acc;
__device__ unsigned int g_cnt;

#define WG_INIT {0.00102838f, 0.00759876f, 0.03600077f, 0.10936069f, \
                 0.21300554f, 0.26601173f, 0.21300554f, 0.10936069f, \
                 0.03600077f, 0.00759876f, 0.00102838f}

// ---- packed f32x2 helpers (sm_100+ PTX; ptxas never auto-fuses these) ----
__device__ __forceinline__ u64 fma2(u64 a, u64 b, u64 c) {
    u64 d; asm("fma.rn.f32x2 %0, %1, %2, %3;" : "=l"(d) : "l"(a), "l"(b), "l"(c)); return d;
}
__device__ __forceinline__ u64 mul2(u64 a, u64 b) {
    u64 d; asm("mul.rn.f32x2 %0, %1, %2;" : "=l"(d) : "l"(a), "l"(b)); return d;
}
__device__ __forceinline__ u64 add2(u64 a, u64 b) {
    u64 d; asm("add.rn.f32x2 %0, %1, %2;" : "=l"(d) : "l"(a), "l"(b)); return d;
}
__device__ __forceinline__ u64 pk2(float lo, float hi) {
    u64 d; asm("mov.b64 %0, {%1, %2};" : "=l"(d) : "f"(lo), "f"(hi)); return d;
}
__device__ __forceinline__ void upk2(u64 v, float& lo, float& hi) {
    asm("mov.b64 {%0, %1}, %2;" : "=f"(lo), "=f"(hi) : "l"(v));
}
__device__ __forceinline__ u64 bc2(float f) {   // broadcast (compile-time folds)
    unsigned int b = __float_as_uint(f);
    return ((u64)b << 32) | b;
}

__global__ void __launch_bounds__(NT, 2) ssim_fused(const float* __restrict__ pred,
                                                    const float* __restrict__ tgt,
                                                    float* __restrict__ out) {
    extern __shared__ float sm[];
    float* wsum = sm + SM_FLOATS;
    const float wg[11] = WG_INIT;
    u64 wgd[11];
    #pragma unroll
    for (int k = 0; k < 11; k++) wgd[k] = bc2(wg[k]);

    const int img  = blockIdx.y;
    const int row0 = blockIdx.x * HT;
    const float* P = pred + (size_t)img * (IMG_W * IMG_H);
    const float* T = tgt  + (size_t)img * (IMG_W * IMG_H);
    const bool interior = (row0 >= 5) && (row0 + HT + 5 <= IMG_H);

    // -------- Vertical pass: column PAIRS packed in f32x2, global -> smem --------
    for (int i2 = threadIdx.x; i2 < SW / 2; i2 += NT) {
        const int x0 = 2 * i2 - 8;           // even; pair (x0, x0+1)
        if (x0 < 0 || x0 >= IMG_W) {         // pairs never straddle the edge
            #pragma unroll
            for (int r = 0; r < HT; r++) {
                ((u64*)(sm + (0 * HT + r) * SW))[i2] = 0ull;
                ((u64*)(sm + (1 * HT + r) * SW))[i2] = 0ull;
                ((u64*)(sm + (2 * HT + r) * SW))[i2] = 0ull;
                ((u64*)(sm + (3 * HT + r) * SW))[i2] = 0ull;
            }
            continue;
        }
        u64 pv[HT + 10], tv[HT + 10];
        if (interior) {
            const float* pc = P + (row0 - 5) * IMG_W + x0;
            const float* tc = T + (row0 - 5) * IMG_W + x0;
            #pragma unroll
            for (int i = 0; i < HT + 10; i++) {
                pv[i] = *(const u64*)(pc + i * IMG_W);   // aligned LDG.64
                tv[i] = *(const u64*)(tc + i * IMG_W);
            }
        } else {
            #pragma unroll
            for (int i = 0; i < HT + 10; i++) {
                const int row = row0 - 5 + i;
                const bool ok = (row >= 0) && (row < IMG_H);
                pv[i] = ok ? *(const u64*)(P + row * IMG_W + x0) : 0ull;
                tv[i] = ok ? *(const u64*)(T + row * IMG_W + x0) : 0ull;
            }
        }
        // phase A: mu_p, mu_t
        #pragma unroll
        for (int r = 0; r < HT; r++) {
            u64 a = 0ull, b = 0ull;
            #pragma unroll
            for (int k = 0; k < 11; k++) {
                a = fma2(wgd[k], pv[r + k], a);
                b = fma2(wgd[k], tv[r + k], b);
            }
            ((u64*)(sm + (0 * HT + r) * SW))[i2] = a;
            ((u64*)(sm + (1 * HT + r) * SW))[i2] = b;
        }
        // phase B: in-place transform  pv <- p^2 + t^2,  tv <- p*t
        #pragma unroll
        for (int i = 0; i < HT + 10; i++) {
            u64 p = pv[i], t = tv[i];
            pv[i] = fma2(t, t, mul2(p, p));
            tv[i] = mul2(p, t);
        }
        // phase C: blur(p^2+t^2), blur(p*t)
        #pragma unroll
        for (int r = 0; r < HT; r++) {
            u64 a = 0ull, b = 0ull;
            #pragma unroll
            for (int k = 0; k < 11; k++) {
                a = fma2(wgd[k], pv[r + k], a);
                b = fma2(wgd[k], tv[r + k], b);
            }
            ((u64*)(sm + (2 * HT + r) * SW))[i2] = a;
            ((u64*)(sm + (3 * HT + r) * SW))[i2] = b;
        }
    }
    __syncthreads();

    // -------- Horizontal pass: 4 outputs x 2 rows packed per task --------
    const u64 TWO2 = bc2(2.0f), C1_2 = bc2(1e-4f), C2_2 = bc2(9e-4f), NEG1 = bc2(-1.0f);
    float acc = 0.f;
    #pragma unroll 1
    for (int task = threadIdx.x; task < (HT / 2) * (IMG_W / 4); task += NT) {  // 512
        const int rp = task >> 7;       // row pair (rows 2rp, 2rp+1)
        const int q  = task & 127;      // quad: outputs x0 = 4q .. 4q+3
        u64 h[4][4];                    // [channel][j], lanes = (rowA, rowB)
        #pragma unroll
        for (int ch = 0; ch < 4; ch++) {
            const float* rowA = sm + (ch * HT + 2 * rp) * SW;
            const float* rowB = rowA + SW;
            float va[20], vb[20];
            #pragma unroll
            for (int b = 0; b < 5; b++) {
                float4 fa = ((const float4*)rowA)[q + b];
                float4 fb = ((const float4*)rowB)[q + b];
                va[4*b+0] = fa.x; va[4*b+1] = fa.y; va[4*b+2] = fa.z; va[4*b+3] = fa.w;
                vb[4*b+0] = fb.x; vb[4*b+1] = fb.y; vb[4*b+2] = fb.z; vb[4*b+3] = fb.w;
            }
            u64 v2[14];                  // taps needed: s = 4q+3 .. 4q+16
            #pragma unroll
            for (int i = 0; i < 14; i++) v2[i] = pk2(va[3 + i], vb[3 + i]);
            #pragma unroll
            for (int j = 0; j < 4; j++) {
                u64 a = 0ull;
                #pragma unroll
                for (int k = 0; k < 11; k++) a = fma2(wgd[k], v2[j + k], a);
                h[ch][j] = a;
            }
        }
        #pragma unroll
        for (int j = 0; j < 4; j++) {
            u64 mx = h[0][j], my = h[1][j], ms = h[2][j], mq = h[3][j];
            u64 mx2 = mul2(mx, mx), my2 = mul2(my, my), mxy = mul2(mx, my);
            u64 t1   = add2(mx2, my2);
            u64 sgs  = fma2(t1,  NEG1, ms);    // (p2+t2 blur) - mx2 - my2
            u64 sgxy = fma2(mxy, NEG1, mq);
            u64 num  = mul2(fma2(TWO2, mxy, C1_2), fma2(TWO2, sgxy, C2_2));
            u64 den  = mul2(add2(t1, C1_2), add2(sgs, C2_2));
            float n0, n1, d0, d1;
            upk2(num, n0, n1); upk2(den, d0, d1);
            acc += __fdividef(n0, d0) + __fdividef(n1, d1);
        }
    }

    // -------- block reduction + last-block finalize --------
    #pragma unroll
    for (int off = 16; off; off >>= 1)
        acc += __shfl_down_sync(0xffffffffu, acc, off);
    if ((threadIdx.x & 31) == 0) wsum[threadIdx.x >> 5] = acc;
    __syncthreads();

    if (threadIdx.x == 0) {
        float s = 0.f;
        #pragma unroll
        for (int i = 0; i < NT / 32; i++) s += wsum[i];
        atomicAdd(&g_acc, (double)s);
        __threadfence();
        unsigned int t = atomicAdd(&g_cnt, 1u);
        if (t == NBLK - 1) {
            double tot = atomicAdd(&g_acc, 0.0);   // coherent read (returns old)
            out[0] = 1.0f - (float)(tot / ((double)N_IMG * IMG_W * IMG_H));
            g_acc = 0.0;    // reset for next graph replay
            g_cnt = 0u;
        }
    }
}

extern "C" void kernel_launch(void* const* d_in, const int* in_sizes, int n_in,
                              void* d_out, int out_size) {
    const float* pred = (const float*)d_in[0];
    const float* tgt  = (const float*)d_in[1];

    // 66 KB dynamic smem > 48 KB default: opt-in (host attribute, capture-safe)
    cudaFuncSetAttribute(ssim_fused, cudaFuncAttributeMaxDynamicSharedMemorySize,
                         SMEM_BYTES);

    dim3 grid(N_STRIPS, N_IMG);
    ssim_fused<<<grid, NT, SMEM_BYTES>>>(pred, tgt, (float*)d_out);
}

// round 13
// speedup vs baseline: 2.7457x; 1.0294x over previous
#include <cuda_runtime.h>

#define IMG_W 512
#define IMG_H 512
#define N_IMG 48            // 16 batch * 3 channels
#define HT 8                // output rows per block strip
#define N_STRIPS (IMG_H / HT)
#define NBLK (N_STRIPS * N_IMG)
#define SW 528              // smem columns: s = x+8; float4-aligned rows
#define NT 256              // 8 warps
#define SM_FLOATS (4 * HT * SW)
#define SMEM_BYTES ((SM_FLOATS + 8) * 4)

// zero-initialized at module load; last block of each launch resets them,
// so every graph replay starts from zero (deterministic).
__device__ double g_acc;
__device__ unsigned int g_cnt;

// literal taps -> FFMA immediate-multiplier form (rt_SMSP = 1, 2x the 3-reg rate)
#define WG_INIT {0.00102838f, 0.00759876f, 0.03600077f, 0.10936069f, \
                 0.21300554f, 0.26601173f, 0.21300554f, 0.10936069f, \
                 0.03600077f, 0.00759876f, 0.00102838f}

// 11-tap conv, 8 outputs, k-outer / r-inner: 8 independent FMA chains (full ILP),
// weight is a compile-time literal in every unrolled statement.
__device__ __forceinline__ void vconv8(const float* __restrict__ v,
                                       float* __restrict__ dst, int stride) {
    const float wg[11] = WG_INIT;
    float a[HT];
    #pragma unroll
    for (int r = 0; r < HT; r++) a[r] = 0.f;
    #pragma unroll
    for (int k = 0; k < 11; k++) {
        #pragma unroll
        for (int r = 0; r < HT; r++) a[r] = fmaf(wg[k], v[r + k], a[r]);
    }
    #pragma unroll
    for (int r = 0; r < HT; r++) dst[r * stride] = a[r];
}

__global__ void __launch_bounds__(NT, 3) ssim_fused(const float* __restrict__ pred,
                                                    const float* __restrict__ tgt,
                                                    float* __restrict__ out) {
    extern __shared__ float sm[];
    float* wsum = sm + SM_FLOATS;
    const float wg[11] = WG_INIT;

    const int img  = blockIdx.y;
    const int row0 = blockIdx.x * HT;
    const float* P = pred + (size_t)img * (IMG_W * IMG_H);
    const float* T = tgt  + (size_t)img * (IMG_W * IMG_H);
    const bool interior = (row0 >= 5) && (row0 + HT + 5 <= IMG_H);

    // -------- Vertical pass (scalar, one column per thread): global -> smem --------
    for (int s = threadIdx.x; s < SW; s += NT) {
        const int x = s - 8;
        if (x < 0 || x >= IMG_W) {
            #pragma unroll
            for (int r = 0; r < HT; r++) {
                sm[(0 * HT + r) * SW + s] = 0.f;
                sm[(1 * HT + r) * SW + s] = 0.f;
                sm[(2 * HT + r) * SW + s] = 0.f;
                sm[(3 * HT + r) * SW + s] = 0.f;
            }
            continue;
        }
        float pv[HT + 10], tv[HT + 10];
        if (interior) {
            const float* pc = P + (row0 - 5) * IMG_W + x;
            const float* tc = T + (row0 - 5) * IMG_W + x;
            #pragma unroll
            for (int i = 0; i < HT + 10; i++) {
                pv[i] = pc[i * IMG_W];
                tv[i] = tc[i * IMG_W];
            }
        } else {
            #pragma unroll
            for (int i = 0; i < HT + 10; i++) {
                const int row = row0 - 5 + i;
                const bool ok = (row >= 0) && (row < IMG_H);
                pv[i] = ok ? P[row * IMG_W + x] : 0.f;
                tv[i] = ok ? T[row * IMG_W + x] : 0.f;
            }
        }
        vconv8(pv, sm + (0 * HT) * SW + s, SW);   // mu_p
        vconv8(tv, sm + (1 * HT) * SW + s, SW);   // mu_t
        // in-place transform: pv <- p^2 + t^2, tv <- p*t (each input used once)
        #pragma unroll
        for (int i = 0; i < HT + 10; i++) {
            const float p = pv[i], t = tv[i];
            pv[i] = fmaf(p, p, t * t);
            tv[i] = p * t;
        }
        vconv8(pv, sm + (2 * HT) * SW + s, SW);   // blur(p^2 + t^2)
        vconv8(tv, sm + (3 * HT) * SW + s, SW);   // blur(p*t)
    }
    __syncthreads();

    // -------- Horizontal pass (4-wide quads) + SSIM formula + reduce --------
    const float C1 = 1e-4f, C2 = 9e-4f;
    float acc = 0.f;
    #pragma unroll 1
    for (int task = threadIdx.x; task < HT * (IMG_W / 4); task += NT) {
        const int r = task >> 7;       // row within strip
        const int q = task & 127;      // quad: outputs x0 = 4q .. 4q+3
        float h[4][4];
        #pragma unroll
        for (int ch = 0; ch < 4; ch++) {
            const float4* rowp = (const float4*)(sm + (ch * HT + r) * SW);
            float v[20];
            #pragma unroll
            for (int b = 0; b < 5; b++) {
                float4 f = rowp[q + b];   // s = 4q..4q+19 covers taps [4q+3, 4q+16]
                v[4 * b + 0] = f.x; v[4 * b + 1] = f.y;
                v[4 * b + 2] = f.z; v[4 * b + 3] = f.w;
            }
            // j-chains are independent (ILP=4); weights are immediates
            #pragma unroll
            for (int j = 0; j < 4; j++) {
                float a = 0.f;
                #pragma unroll
                for (int k = 0; k < 11; k++) a = fmaf(wg[k], v[3 + j + k], a);
                h[ch][j] = a;
            }
        }
        #pragma unroll
        for (int j = 0; j < 4; j++) {
            float mx  = h[0][j], my = h[1][j];
            float mx2 = mx * mx, my2 = my * my, mxy = mx * my;
            float sgs  = h[2][j] - mx2 - my2;   // sg_x + sg_y
            float sgxy = h[3][j] - mxy;
            float num = (2.f * mxy + C1) * (2.f * sgxy + C2);
            float den = (mx2 + my2 + C1) * (sgs + C2);
            acc += __fdividef(num, den);
        }
    }

    // -------- block reduction + last-block finalize --------
    #pragma unroll
    for (int off = 16; off; off >>= 1)
        acc += __shfl_down_sync(0xffffffffu, acc, off);
    if ((threadIdx.x & 31) == 0) wsum[threadIdx.x >> 5] = acc;
    __syncthreads();

    if (threadIdx.x == 0) {
        float s = 0.f;
        #pragma unroll
        for (int i = 0; i < NT / 32; i++) s += wsum[i];
        atomicAdd(&g_acc, (double)s);
        __threadfence();
        unsigned int t = atomicAdd(&g_cnt, 1u);
        if (t == NBLK - 1) {
            double tot = atomicAdd(&g_acc, 0.0);   // coherent read (returns old)
            out[0] = 1.0f - (float)(tot / ((double)N_IMG * IMG_W * IMG_H));
            g_acc = 0.0;    // reset for next graph replay
            g_cnt = 0u;
        }
    }
}

extern "C" void kernel_launch(void* const* d_in, const int* in_sizes, int n_in,
                              void* d_out, int out_size) {
    const float* pred = (const float*)d_in[0];
    const float* tgt  = (const float*)d_in[1];

    // 66 KB dynamic smem > 48 KB default: opt-in (host attribute, capture-safe)
    cudaFuncSetAttribute(ssim_fused, cudaFuncAttributeMaxDynamicSharedMemorySize,
                         SMEM_BYTES);

    dim3 grid(N_STRIPS, N_IMG);
    ssim_fused<<<grid, NT, SMEM_BYTES>>>(pred, tgt, (float*)d_out);
}